// round 6
// baseline (speedup 1.0000x reference)
#include <cuda_runtime.h>
#include <cstdint>

// Problem constants (fixed shapes from reference)
#define B_    16
#define N_    256
#define EDIM  1024
#define F_    2
#define C_    512          // EDIM / F_
#define NE    4096         // codebook size
#define NTOK  8192         // B_*F_*N_  (tokens total, also F_*NE proto rows)
#define BN    4096         // B_*N_ tokens per codebook
#define ZQ_ELEMS 4194304   // B_*N_*EDIM
#define EPS_  1e-12f

// ---- device scratch (no allocations allowed) ----
__device__ unsigned long long g_best[NTOK];   // packed (ord(d-min) , 0xFFFFFFFF-col)
__device__ float g_invp[NTOK];                // 1/max(||emb_row||,eps), full 8192-row table
__device__ float g_nrmz[NTOK];                // max(||zf_token||,eps)
__device__ float g_loss_part[NTOK];           // per-token loss partials

// float -> order-preserving uint32
__device__ __forceinline__ unsigned f2ord(float f) {
    unsigned u = __float_as_uint(f);
    return (u & 0x80000000u) ? ~u : (u | 0x80000000u);
}

// ---------------------------------------------------------------------------
// 0) init: clear argmin keys
// ---------------------------------------------------------------------------
__global__ void init_kernel() {
    int i = blockIdx.x * blockDim.x + threadIdx.x;
    if (i < NTOK) g_best[i] = 0ull;
}

// ---------------------------------------------------------------------------
// 1) norms: one warp per row. warps [0,8192): prototype rows; [8192,16384): tokens
// ---------------------------------------------------------------------------
__global__ void norms_kernel(const float* __restrict__ z, const float* __restrict__ emb) {
    int gw   = (blockIdx.x * blockDim.x + threadIdx.x) >> 5;
    int lane = threadIdx.x & 31;
    const float* p;
    if (gw < NTOK) {
        p = emb + (size_t)gw * C_;
    } else {
        int t  = gw - NTOK;
        int f  = t >> 12;
        int bn = t & (BN - 1);
        p = z + (size_t)bn * EDIM + f * C_;
    }
    float s = 0.f;
    #pragma unroll
    for (int q = 0; q < 4; q++) {
        float4 v = *reinterpret_cast<const float4*>(p + lane * 4 + q * 128);
        s += v.x * v.x + v.y * v.y + v.z * v.z + v.w * v.w;
    }
    #pragma unroll
    for (int o = 16; o > 0; o >>= 1) s += __shfl_xor_sync(0xFFFFFFFFu, s, o);
    if (lane == 0) {
        float nrm = fmaxf(sqrtf(s), EPS_);
        if (gw < NTOK) g_invp[gw] = 1.0f / nrm;
        else           g_nrmz[gw - NTOK] = nrm;
    }
}

// ---------------------------------------------------------------------------
// 2) fused GEMM + argmin:  s = (zf . p) * invp * invz ; d = 2 - 2s ; argmin over m
//    128x128 block tile, K-chunks of 32, 8x8 register tile, 256 threads.
// ---------------------------------------------------------------------------
#define TM 128
#define TN 128
#define KC 32
#define PAD 4

__global__ __launch_bounds__(256, 2)
void gemm_argmin_kernel(const float* __restrict__ z, const float* __restrict__ emb) {
    __shared__ float As[KC][TM + PAD];
    __shared__ float Bs[KC][TN + PAD];

    const int f  = blockIdx.z;
    const int m0 = blockIdx.y * TM;   // token tile (within codebook, 0..4095)
    const int n0 = blockIdx.x * TN;   // proto tile (within codebook)
    const int tid = threadIdx.x;
    const int tx = tid & 15;
    const int ty = tid >> 4;

    const float* Aptr = z   + (size_t)m0 * EDIM + f * C_;           // row stride EDIM
    const float* Bptr = emb + ((size_t)(f * NE + n0)) * C_;         // row stride C_

    float acc[8][8];
    #pragma unroll
    for (int i = 0; i < 8; i++)
        #pragma unroll
        for (int j = 0; j < 8; j++) acc[i][j] = 0.f;

    for (int k0 = 0; k0 < C_; k0 += KC) {
        #pragma unroll
        for (int i = 0; i < 4; i++) {
            int idx = tid + i * 256;
            int row = idx >> 3;
            int c4  = (idx & 7) * 4;
            float4 v = *reinterpret_cast<const float4*>(Aptr + (size_t)row * EDIM + k0 + c4);
            As[c4 + 0][row] = v.x; As[c4 + 1][row] = v.y;
            As[c4 + 2][row] = v.z; As[c4 + 3][row] = v.w;
        }
        #pragma unroll
        for (int i = 0; i < 4; i++) {
            int idx = tid + i * 256;
            int row = idx >> 3;
            int c4  = (idx & 7) * 4;
            float4 v = *reinterpret_cast<const float4*>(Bptr + (size_t)row * C_ + k0 + c4);
            Bs[c4 + 0][row] = v.x; Bs[c4 + 1][row] = v.y;
            Bs[c4 + 2][row] = v.z; Bs[c4 + 3][row] = v.w;
        }
        __syncthreads();
        #pragma unroll
        for (int k = 0; k < KC; k++) {
            float a[8], b[8];
            *reinterpret_cast<float4*>(&a[0]) = *reinterpret_cast<const float4*>(&As[k][ty * 8]);
            *reinterpret_cast<float4*>(&a[4]) = *reinterpret_cast<const float4*>(&As[k][ty * 8 + 4]);
            *reinterpret_cast<float4*>(&b[0]) = *reinterpret_cast<const float4*>(&Bs[k][tx * 8]);
            *reinterpret_cast<float4*>(&b[4]) = *reinterpret_cast<const float4*>(&Bs[k][tx * 8 + 4]);
            #pragma unroll
            for (int i = 0; i < 8; i++)
                #pragma unroll
                for (int j = 0; j < 8; j++) acc[i][j] += a[i] * b[j];
        }
        __syncthreads();
    }

    // epilogue: scale by prototype & token inverse norms, d = 2-2s, argmin with
    // first-index tie-break; reduce across the 16 tx lanes sharing a row group.
    float invp[8];
    #pragma unroll
    for (int j = 0; j < 8; j++) invp[j] = g_invp[f * NE + n0 + tx * 8 + j];

    #pragma unroll
    for (int i = 0; i < 8; i++) {
        int trow = f * BN + m0 + ty * 8 + i;          // token id
        float invz = 1.0f / g_nrmz[trow];
        unsigned long long key = 0ull;
        #pragma unroll
        for (int j = 0; j < 8; j++) {
            float s = acc[i][j] * invp[j] * invz;
            float d = __fsub_rn(2.0f, __fmul_rn(2.0f, s));   // match reference rounding
            unsigned ord = ~f2ord(d);                        // bigger = smaller d
            unsigned col = (unsigned)(n0 + tx * 8 + j);
            unsigned long long k2 = ((unsigned long long)ord << 32) | (0xFFFFFFFFu - col);
            if (k2 > key) key = k2;
        }
        #pragma unroll
        for (int o = 8; o >= 1; o >>= 1) {
            unsigned long long other = __shfl_xor_sync(0xFFFFFFFFu, key, o);
            if (other > key) key = other;
        }
        if ((tid & 15) == 0) atomicMax(&g_best[trow], key);
    }
}

// ---------------------------------------------------------------------------
// 3) gather + output + per-token loss partial. One block (128 thr) per token.
// ---------------------------------------------------------------------------
__global__ void gather_kernel(const float* __restrict__ z, const float* __restrict__ emb,
                              float* __restrict__ out, int out_size) {
    int t  = blockIdx.x;
    int f  = t >> 12;
    int bn = t & (BN - 1);
    int b  = bn >> 8;
    int n  = bn & 255;

    unsigned m = 0xFFFFFFFFu - (unsigned)(g_best[t] & 0xFFFFFFFFull);  // in [0, NE)
    float qscale = g_invp[m];       // gather from FULL table rows [0,4096) — matches reference
    float nz     = g_nrmz[t];

    int j = threadIdx.x * 4;
    float4 vq = *reinterpret_cast<const float4*>(emb + (size_t)m * C_ + j);
    float4 vz = *reinterpret_cast<const float4*>(z + (size_t)bn * EDIM + f * C_ + j);

    float o[4], lsum = 0.f;
    {
        float qv[4] = {vq.x, vq.y, vq.z, vq.w};
        float zv[4] = {vz.x, vz.y, vz.z, vz.w};
        #pragma unroll
        for (int q = 0; q < 4; q++) {
            float zq = __fmul_rn(qv[q], qscale);
            float zn = __fdiv_rn(zv[q], nz);
            float dd = __fsub_rn(zq, zn);
            o[q] = __fadd_rn(zn, dd);        // straight-through, exact reference rounding
            lsum += dd * dd;
        }
    }
    int obase = bn * EDIM + f * C_ + j;
    if (obase + 3 < out_size) {
        float4 ov; ov.x = o[0]; ov.y = o[1]; ov.z = o[2]; ov.w = o[3];
        *reinterpret_cast<float4*>(out + obase) = ov;
    }

    // deterministic block reduction of lsum (4 warps)
    #pragma unroll
    for (int ofs = 16; ofs > 0; ofs >>= 1) lsum += __shfl_xor_sync(0xFFFFFFFFu, lsum, ofs);
    __shared__ float sw[4];
    int lane = threadIdx.x & 31, wid = threadIdx.x >> 5;
    if (lane == 0) sw[wid] = lsum;
    __syncthreads();
    if (threadIdx.x == 0) {
        g_loss_part[t] = (sw[0] + sw[1]) + (sw[2] + sw[3]);
        int p = ZQ_ELEMS + 1 + ((b * 2 + f) << 8) + n;   // indices flat (b,f,n)
        if (p < out_size) out[p] = (float)m;
    }
}

// ---------------------------------------------------------------------------
// 4) final loss: deterministic fixed-order reduction of 8192 partials.
// ---------------------------------------------------------------------------
__global__ void loss_kernel(float* __restrict__ out, int out_size) {
    __shared__ float sh[256];
    float s = 0.f;
    for (int i = threadIdx.x; i < NTOK; i += 256) s += g_loss_part[i];
    sh[threadIdx.x] = s;
    __syncthreads();
    for (int st = 128; st > 0; st >>= 1) {
        if (threadIdx.x < st) sh[threadIdx.x] += sh[threadIdx.x + st];
        __syncthreads();
    }
    if (threadIdx.x == 0 && out_size > ZQ_ELEMS) {
        float mean = sh[0] / (float)ZQ_ELEMS;
        out[ZQ_ELEMS] = __fadd_rn(__fmul_rn(0.25f, mean), mean);  // BETA*mean + mean
    }
}

// ---------------------------------------------------------------------------
extern "C" void kernel_launch(void* const* d_in, const int* in_sizes, int n_in,
                              void* d_out, int out_size) {
    const float* z   = (const float*)d_in[0];
    const float* emb = (const float*)d_in[1];
    float* out = (float*)d_out;
    (void)in_sizes; (void)n_in;

    init_kernel<<<(NTOK + 255) / 256, 256>>>();
    norms_kernel<<<(2 * NTOK) / 8, 256>>>(z, emb);                 // 8 warps/block
    gemm_argmin_kernel<<<dim3(NE / TN, BN / TM, F_), 256>>>(z, emb);
    gather_kernel<<<NTOK, 128>>>(z, emb, out, out_size);
    loss_kernel<<<1, 256>>>(out, out_size);
}

// round 7
// speedup vs baseline: 1.0020x; 1.0020x over previous
#include <cuda_runtime.h>
#include <cstdint>

// Problem constants (fixed shapes from reference)
#define B_    16
#define N_    256
#define EDIM  1024
#define F_    2
#define C_    512          // EDIM / F_
#define NE    4096         // codebook size
#define NTOK  8192         // B_*F_*N_  (tokens total, also F_*NE proto rows)
#define BN    4096         // B_*N_ tokens per codebook
#define ZQ_ELEMS 4194304   // B_*N_*EDIM
#define EPS_  1e-12f

// ---- device scratch (no allocations allowed) ----
__device__ unsigned long long g_best[NTOK];   // packed (ord(d-min) , 0xFFFFFFFF-col)
__device__ float g_invp[NTOK];                // 1/max(||emb_row||,eps), full 8192-row table
__device__ float g_nrmz[NTOK];                // max(||zf_token||,eps)
__device__ float g_loss_part[NTOK];           // per-token loss partials

// float -> order-preserving uint32
__device__ __forceinline__ unsigned f2ord(float f) {
    unsigned u = __float_as_uint(f);
    return (u & 0x80000000u) ? ~u : (u | 0x80000000u);
}

// ---------------------------------------------------------------------------
// 0) init: clear argmin keys
// ---------------------------------------------------------------------------
__global__ void init_kernel() {
    int i = blockIdx.x * blockDim.x + threadIdx.x;
    if (i < NTOK) g_best[i] = 0ull;
}

// ---------------------------------------------------------------------------
// 1) norms: one warp per row. warps [0,8192): prototype rows; [8192,16384): tokens
// ---------------------------------------------------------------------------
__global__ void norms_kernel(const float* __restrict__ z, const float* __restrict__ emb) {
    int gw   = (blockIdx.x * blockDim.x + threadIdx.x) >> 5;
    int lane = threadIdx.x & 31;
    const float* p;
    if (gw < NTOK) {
        p = emb + (size_t)gw * C_;
    } else {
        int t  = gw - NTOK;
        int f  = t >> 12;
        int bn = t & (BN - 1);
        p = z + (size_t)bn * EDIM + f * C_;
    }
    float s = 0.f;
    #pragma unroll
    for (int q = 0; q < 4; q++) {
        float4 v = *reinterpret_cast<const float4*>(p + lane * 4 + q * 128);
        s += v.x * v.x + v.y * v.y + v.z * v.z + v.w * v.w;
    }
    #pragma unroll
    for (int o = 16; o > 0; o >>= 1) s += __shfl_xor_sync(0xFFFFFFFFu, s, o);
    if (lane == 0) {
        float nrm = fmaxf(sqrtf(s), EPS_);
        if (gw < NTOK) g_invp[gw] = 1.0f / nrm;
        else           g_nrmz[gw - NTOK] = nrm;
    }
}

// ---------------------------------------------------------------------------
// 2) fused GEMM + argmin:  s = (zf . p) * invp * invz ; d = 2 - 2s ; argmin over m
//    128x128 block tile, K-chunks of 32, 8x8 register tile, 256 threads.
// ---------------------------------------------------------------------------
#define TM 128
#define TN 128
#define KC 32
#define PAD 4

__global__ __launch_bounds__(256, 2)
void gemm_argmin_kernel(const float* __restrict__ z, const float* __restrict__ emb) {
    __shared__ float As[KC][TM + PAD];
    __shared__ float Bs[KC][TN + PAD];

    const int f  = blockIdx.z;
    const int m0 = blockIdx.y * TM;   // token tile (within codebook, 0..4095)
    const int n0 = blockIdx.x * TN;   // proto tile (within codebook)
    const int tid = threadIdx.x;
    const int tx = tid & 15;
    const int ty = tid >> 4;

    const float* Aptr = z   + (size_t)m0 * EDIM + f * C_;           // row stride EDIM
    const float* Bptr = emb + ((size_t)(f * NE + n0)) * C_;         // row stride C_

    float acc[8][8];
    #pragma unroll
    for (int i = 0; i < 8; i++)
        #pragma unroll
        for (int j = 0; j < 8; j++) acc[i][j] = 0.f;

    for (int k0 = 0; k0 < C_; k0 += KC) {
        #pragma unroll
        for (int i = 0; i < 4; i++) {
            int idx = tid + i * 256;
            int row = idx >> 3;
            int c4  = (idx & 7) * 4;
            float4 v = *reinterpret_cast<const float4*>(Aptr + (size_t)row * EDIM + k0 + c4);
            As[c4 + 0][row] = v.x; As[c4 + 1][row] = v.y;
            As[c4 + 2][row] = v.z; As[c4 + 3][row] = v.w;
        }
        #pragma unroll
        for (int i = 0; i < 4; i++) {
            int idx = tid + i * 256;
            int row = idx >> 3;
            int c4  = (idx & 7) * 4;
            float4 v = *reinterpret_cast<const float4*>(Bptr + (size_t)row * C_ + k0 + c4);
            Bs[c4 + 0][row] = v.x; Bs[c4 + 1][row] = v.y;
            Bs[c4 + 2][row] = v.z; Bs[c4 + 3][row] = v.w;
        }
        __syncthreads();
        #pragma unroll
        for (int k = 0; k < KC; k++) {
            float a[8], b[8];
            *reinterpret_cast<float4*>(&a[0]) = *reinterpret_cast<const float4*>(&As[k][ty * 8]);
            *reinterpret_cast<float4*>(&a[4]) = *reinterpret_cast<const float4*>(&As[k][ty * 8 + 4]);
            *reinterpret_cast<float4*>(&b[0]) = *reinterpret_cast<const float4*>(&Bs[k][tx * 8]);
            *reinterpret_cast<float4*>(&b[4]) = *reinterpret_cast<const float4*>(&Bs[k][tx * 8 + 4]);
            #pragma unroll
            for (int i = 0; i < 8; i++)
                #pragma unroll
                for (int j = 0; j < 8; j++) acc[i][j] += a[i] * b[j];
        }
        __syncthreads();
    }

    // epilogue: scale by prototype & token inverse norms, d = 2-2s, argmin with
    // first-index tie-break; reduce across the 16 tx lanes sharing a row group.
    float invp[8];
    #pragma unroll
    for (int j = 0; j < 8; j++) invp[j] = g_invp[f * NE + n0 + tx * 8 + j];

    #pragma unroll
    for (int i = 0; i < 8; i++) {
        int trow = f * BN + m0 + ty * 8 + i;          // token id
        float invz = 1.0f / g_nrmz[trow];
        unsigned long long key = 0ull;
        #pragma unroll
        for (int j = 0; j < 8; j++) {
            float s = acc[i][j] * invp[j] * invz;
            float d = __fsub_rn(2.0f, __fmul_rn(2.0f, s));   // match reference rounding
            unsigned ord = ~f2ord(d);                        // bigger = smaller d
            unsigned col = (unsigned)(n0 + tx * 8 + j);
            unsigned long long k2 = ((unsigned long long)ord << 32) | (0xFFFFFFFFu - col);
            if (k2 > key) key = k2;
        }
        #pragma unroll
        for (int o = 8; o >= 1; o >>= 1) {
            unsigned long long other = __shfl_xor_sync(0xFFFFFFFFu, key, o);
            if (other > key) key = other;
        }
        if ((tid & 15) == 0) atomicMax(&g_best[trow], key);
    }
}

// ---------------------------------------------------------------------------
// 3) gather + output + per-token loss partial. One block (128 thr) per token.
// ---------------------------------------------------------------------------
__global__ void gather_kernel(const float* __restrict__ z, const float* __restrict__ emb,
                              float* __restrict__ out, int out_size) {
    int t  = blockIdx.x;
    int f  = t >> 12;
    int bn = t & (BN - 1);
    int b  = bn >> 8;
    int n  = bn & 255;

    unsigned m = 0xFFFFFFFFu - (unsigned)(g_best[t] & 0xFFFFFFFFull);  // in [0, NE)
    float qscale = g_invp[m];       // gather from FULL table rows [0,4096) — matches reference
    float nz     = g_nrmz[t];

    int j = threadIdx.x * 4;
    float4 vq = *reinterpret_cast<const float4*>(emb + (size_t)m * C_ + j);
    float4 vz = *reinterpret_cast<const float4*>(z + (size_t)bn * EDIM + f * C_ + j);

    float o[4], lsum = 0.f;
    {
        float qv[4] = {vq.x, vq.y, vq.z, vq.w};
        float zv[4] = {vz.x, vz.y, vz.z, vz.w};
        #pragma unroll
        for (int q = 0; q < 4; q++) {
            float zq = __fmul_rn(qv[q], qscale);
            float zn = __fdiv_rn(zv[q], nz);
            float dd = __fsub_rn(zq, zn);
            o[q] = __fadd_rn(zn, dd);        // straight-through, exact reference rounding
            lsum += dd * dd;
        }
    }
    int obase = bn * EDIM + f * C_ + j;
    if (obase + 3 < out_size) {
        float4 ov; ov.x = o[0]; ov.y = o[1]; ov.z = o[2]; ov.w = o[3];
        *reinterpret_cast<float4*>(out + obase) = ov;
    }

    // deterministic block reduction of lsum (4 warps)
    #pragma unroll
    for (int ofs = 16; ofs > 0; ofs >>= 1) lsum += __shfl_xor_sync(0xFFFFFFFFu, lsum, ofs);
    __shared__ float sw[4];
    int lane = threadIdx.x & 31, wid = threadIdx.x >> 5;
    if (lane == 0) sw[wid] = lsum;
    __syncthreads();
    if (threadIdx.x == 0) {
        g_loss_part[t] = (sw[0] + sw[1]) + (sw[2] + sw[3]);
        int p = ZQ_ELEMS + 1 + ((b * 2 + f) << 8) + n;   // indices flat (b,f,n)
        if (p < out_size) out[p] = (float)m;
    }
}

// ---------------------------------------------------------------------------
// 4) final loss: deterministic fixed-order reduction of 8192 partials.
// ---------------------------------------------------------------------------
__global__ void loss_kernel(float* __restrict__ out, int out_size) {
    __shared__ float sh[256];
    float s = 0.f;
    for (int i = threadIdx.x; i < NTOK; i += 256) s += g_loss_part[i];
    sh[threadIdx.x] = s;
    __syncthreads();
    for (int st = 128; st > 0; st >>= 1) {
        if (threadIdx.x < st) sh[threadIdx.x] += sh[threadIdx.x + st];
        __syncthreads();
    }
    if (threadIdx.x == 0 && out_size > ZQ_ELEMS) {
        float mean = sh[0] / (float)ZQ_ELEMS;
        out[ZQ_ELEMS] = __fadd_rn(__fmul_rn(0.25f, mean), mean);  // BETA*mean + mean
    }
}

// ---------------------------------------------------------------------------
extern "C" void kernel_launch(void* const* d_in, const int* in_sizes, int n_in,
                              void* d_out, int out_size) {
    const float* z   = (const float*)d_in[0];
    const float* emb = (const float*)d_in[1];
    float* out = (float*)d_out;
    (void)in_sizes; (void)n_in;

    init_kernel<<<(NTOK + 255) / 256, 256>>>();
    norms_kernel<<<(2 * NTOK) / 8, 256>>>(z, emb);                 // 8 warps/block
    gemm_argmin_kernel<<<dim3(NE / TN, BN / TM, F_), 256>>>(z, emb);
    gather_kernel<<<NTOK, 128>>>(z, emb, out, out_size);
    loss_kernel<<<1, 256>>>(out, out_size);
}

// round 8
// speedup vs baseline: 2.8121x; 2.8065x over previous
#include <cuda_runtime.h>
#include <cuda_bf16.h>
#include <mma.h>
#include <cstdint>

using namespace nvcuda;

// Problem constants (fixed shapes from reference)
#define B_    16
#define N_    256
#define EDIM  1024
#define F_    2
#define C_    512          // EDIM / F_
#define NE    4096         // codebook size
#define NTOK  8192         // B_*F_*N_  (tokens total, also F_*NE proto rows)
#define BN    4096         // B_*N_ tokens per codebook
#define ZQ_ELEMS 4194304   // B_*N_*EDIM
#define EPS_  1e-12f
#define MARGIN 0.03f       // > 2x worst-case bf16 dot error bound in d-space

// ---- device scratch (static: no runtime allocations) ----
__device__ float g_invp[NTOK];                 // 1/max(||emb_row||,eps)
__device__ float g_nrmz[NTOK];                 // max(||zf_token||,eps)
__device__ float g_loss_part[NTOK];
__device__ unsigned g_idx[NTOK];               // final selected code per token
__device__ __nv_bfloat16 g_zbf[NTOK * C_];     // normalized z in bf16  [f][bn][c]
__device__ __nv_bfloat16 g_pbf[NTOK * C_];     // normalized protos bf16 [f][n][c]
__device__ float g_s[(size_t)NTOK * NE];       // approx cos matrix [f][bn][n] (128MB)

// float -> order-preserving uint32
__device__ __forceinline__ unsigned f2ord(float f) {
    unsigned u = __float_as_uint(f);
    return (u & 0x80000000u) ? ~u : (u | 0x80000000u);
}

// ---------------------------------------------------------------------------
// 1) norms: one warp per row. warps [0,8192): prototype rows; [8192,16384): tokens
// ---------------------------------------------------------------------------
__global__ void norms_kernel(const float* __restrict__ z, const float* __restrict__ emb) {
    int gw   = (blockIdx.x * blockDim.x + threadIdx.x) >> 5;
    int lane = threadIdx.x & 31;
    const float* p;
    if (gw < NTOK) {
        p = emb + (size_t)gw * C_;
    } else {
        int t  = gw - NTOK;
        int f  = t >> 12;
        int bn = t & (BN - 1);
        p = z + (size_t)bn * EDIM + f * C_;
    }
    float s = 0.f;
    #pragma unroll
    for (int q = 0; q < 4; q++) {
        float4 v = *reinterpret_cast<const float4*>(p + lane * 4 + q * 128);
        s += v.x * v.x + v.y * v.y + v.z * v.z + v.w * v.w;
    }
    #pragma unroll
    for (int o = 16; o > 0; o >>= 1) s += __shfl_xor_sync(0xFFFFFFFFu, s, o);
    if (lane == 0) {
        float nrm = fmaxf(sqrtf(s), EPS_);
        if (gw < NTOK) g_invp[gw] = 1.0f / nrm;
        else           g_nrmz[gw - NTOK] = nrm;
    }
}

// ---------------------------------------------------------------------------
// 2) convert to bf16 with norms folded in. 4 elems / thread.
// ---------------------------------------------------------------------------
__global__ void convA_kernel(const float* __restrict__ z) {
    int i = blockIdx.x * blockDim.x + threadIdx.x;
    int e = i << 2;                       // element index into [f][bn][c]
    if (e >= NTOK * C_) return;
    int t  = e >> 9;                      // token id f*4096+bn
    int k  = e & (C_ - 1);
    int f  = t >> 12;
    int bn = t & (BN - 1);
    float inv = 1.0f / g_nrmz[t];
    float4 v = *reinterpret_cast<const float4*>(z + (size_t)bn * EDIM + f * C_ + k);
    __nv_bfloat162 lo = __floats2bfloat162_rn(v.x * inv, v.y * inv);
    __nv_bfloat162 hi = __floats2bfloat162_rn(v.z * inv, v.w * inv);
    *reinterpret_cast<__nv_bfloat162*>(g_zbf + e)     = lo;
    *reinterpret_cast<__nv_bfloat162*>(g_zbf + e + 2) = hi;
}

__global__ void convB_kernel(const float* __restrict__ emb) {
    int i = blockIdx.x * blockDim.x + threadIdx.x;
    int e = i << 2;
    if (e >= NTOK * C_) return;
    int r = e >> 9;                       // emb row (= f*NE+n)
    float sc = g_invp[r];
    float4 v = *reinterpret_cast<const float4*>(emb + e);
    __nv_bfloat162 lo = __floats2bfloat162_rn(v.x * sc, v.y * sc);
    __nv_bfloat162 hi = __floats2bfloat162_rn(v.z * sc, v.w * sc);
    *reinterpret_cast<__nv_bfloat162*>(g_pbf + e)     = lo;
    *reinterpret_cast<__nv_bfloat162*>(g_pbf + e + 2) = hi;
}

// ---------------------------------------------------------------------------
// 3) bf16 tensor-core GEMM: s = zn . pn^T  (per codebook), store fp32 cos matrix.
//    128x128 block tile, 8 warps (2x4), each warp 64x32 (4x2 wmma 16x16x16 frags).
// ---------------------------------------------------------------------------
#define GK 32
#define LDPAD 48   // padded shared row (halves): mult of 8, rows 96B = 32B-aligned

__global__ __launch_bounds__(256)
void wmma_gemm_kernel() {
    __shared__ __nv_bfloat16 As[128][LDPAD];
    __shared__ __nv_bfloat16 Bs[128][LDPAD];

    const int f  = blockIdx.z;
    const int m0 = blockIdx.y * 128;
    const int n0 = blockIdx.x * 128;
    const __nv_bfloat16* A = g_zbf + ((size_t)f * BN + m0) * C_;
    const __nv_bfloat16* B = g_pbf + ((size_t)f * NE + n0) * C_;

    const int warp = threadIdx.x >> 5;
    const int wm = warp >> 2;        // 0..1  (64-row slab)
    const int wn = warp & 3;         // 0..3  (32-col slab)

    wmma::fragment<wmma::accumulator, 16, 16, 16, float> acc[4][2];
    #pragma unroll
    for (int i = 0; i < 4; i++)
        #pragma unroll
        for (int j = 0; j < 2; j++) wmma::fill_fragment(acc[i][j], 0.0f);

    for (int k0 = 0; k0 < C_; k0 += GK) {
        // stage A,B chunks (128 rows x 32 cols) into shared: 512 uint4 each
        #pragma unroll
        for (int r = 0; r < 2; r++) {
            int idx = threadIdx.x + r * 256;      // 0..511
            int row = idx >> 2;
            int col = (idx & 3) * 8;
            *reinterpret_cast<uint4*>(&As[row][col]) =
                *reinterpret_cast<const uint4*>(A + (size_t)row * C_ + k0 + col);
            *reinterpret_cast<uint4*>(&Bs[row][col]) =
                *reinterpret_cast<const uint4*>(B + (size_t)row * C_ + k0 + col);
        }
        __syncthreads();

        #pragma unroll
        for (int kk = 0; kk < GK; kk += 16) {
            wmma::fragment<wmma::matrix_a, 16, 16, 16, __nv_bfloat16, wmma::row_major> af[4];
            wmma::fragment<wmma::matrix_b, 16, 16, 16, __nv_bfloat16, wmma::col_major> bf[2];
            #pragma unroll
            for (int i = 0; i < 4; i++)
                wmma::load_matrix_sync(af[i], &As[wm * 64 + i * 16][kk], LDPAD);
            #pragma unroll
            for (int j = 0; j < 2; j++)
                wmma::load_matrix_sync(bf[j], &Bs[wn * 32 + j * 16][kk], LDPAD);
            #pragma unroll
            for (int i = 0; i < 4; i++)
                #pragma unroll
                for (int j = 0; j < 2; j++)
                    wmma::mma_sync(acc[i][j], af[i], bf[j], acc[i][j]);
        }
        __syncthreads();
    }

    #pragma unroll
    for (int i = 0; i < 4; i++)
        #pragma unroll
        for (int j = 0; j < 2; j++) {
            float* dst = g_s + ((size_t)f * BN + m0 + wm * 64 + i * 16) * NE
                             + n0 + wn * 32 + j * 16;
            wmma::store_matrix_sync(dst, acc[i][j], NE, wmma::mem_row_major);
        }
}

// ---------------------------------------------------------------------------
// 4) select: per token — approx min over 4096, margin-collect candidates,
//    exact fp32 rescore with reference rounding + lowest-index tie-break.
// ---------------------------------------------------------------------------
__global__ __launch_bounds__(256)
void select_kernel(const float* __restrict__ z, const float* __restrict__ emb) {
    const int t  = blockIdx.x;
    const int f  = t >> 12;
    const int bn = t & (BN - 1);
    const float* srow = g_s + ((size_t)t << 12);

    float dv[16];
    float lmin = 1e30f;
    #pragma unroll
    for (int q = 0; q < 16; q++) {
        float a = srow[threadIdx.x + q * 256];
        float d = __fsub_rn(2.0f, __fmul_rn(2.0f, a));
        dv[q] = d;
        lmin = fminf(lmin, d);
    }
    __shared__ float red[256];
    red[threadIdx.x] = lmin;
    __syncthreads();
    #pragma unroll
    for (int st = 128; st > 0; st >>= 1) {
        if (threadIdx.x < st) red[threadIdx.x] = fminf(red[threadIdx.x], red[threadIdx.x + st]);
        __syncthreads();
    }
    const float dmin = red[0];

    __shared__ int cand[256];
    __shared__ int cnt;
    __shared__ unsigned long long bestk;
    __shared__ float ztok[C_];
    if (threadIdx.x == 0) { cnt = 0; bestk = 0ull; }
    __syncthreads();

    #pragma unroll
    for (int q = 0; q < 16; q++) {
        if (dv[q] <= dmin + MARGIN) {
            int p = atomicAdd(&cnt, 1);
            if (p < 256) cand[p] = threadIdx.x + q * 256;
        }
    }
    for (int i = threadIdx.x; i < C_; i += 256)
        ztok[i] = z[(size_t)bn * EDIM + f * C_ + i];
    __syncthreads();

    const float invz = 1.0f / g_nrmz[t];
    const int nc = min(cnt, 256);
    const int warp = threadIdx.x >> 5, lane = threadIdx.x & 31;

    for (int c = warp; c < nc; c += 8) {
        int j = cand[c];
        const float* er = emb + (size_t)(f * NE + j) * C_;
        float s = 0.f;
        for (int i = lane; i < C_; i += 32) s += ztok[i] * er[i];
        #pragma unroll
        for (int o = 16; o > 0; o >>= 1) s += __shfl_xor_sync(0xFFFFFFFFu, s, o);
        if (lane == 0) {
            s = s * g_invp[f * NE + j] * invz;
            float d = __fsub_rn(2.0f, __fmul_rn(2.0f, s));
            unsigned long long key =
                ((unsigned long long)(~f2ord(d)) << 32) | (0xFFFFFFFFu - (unsigned)j);
            atomicMax(&bestk, key);
        }
    }
    __syncthreads();
    if (threadIdx.x == 0)
        g_idx[t] = 0xFFFFFFFFu - (unsigned)(bestk & 0xFFFFFFFFull);
}

// ---------------------------------------------------------------------------
// 5) gather + output + per-token loss partial. One block (128 thr) per token.
// ---------------------------------------------------------------------------
__global__ void gather_kernel(const float* __restrict__ z, const float* __restrict__ emb,
                              float* __restrict__ out, int out_size) {
    int t  = blockIdx.x;
    int f  = t >> 12;
    int bn = t & (BN - 1);
    int b  = bn >> 8;
    int n  = bn & 255;

    unsigned m = g_idx[t];          // in [0, NE) — gathers from FULL table rows
    float qscale = g_invp[m];
    float nz     = g_nrmz[t];

    int j = threadIdx.x * 4;
    float4 vq = *reinterpret_cast<const float4*>(emb + (size_t)m * C_ + j);
    float4 vz = *reinterpret_cast<const float4*>(z + (size_t)bn * EDIM + f * C_ + j);

    float o[4], lsum = 0.f;
    {
        float qv[4] = {vq.x, vq.y, vq.z, vq.w};
        float zv[4] = {vz.x, vz.y, vz.z, vz.w};
        #pragma unroll
        for (int q = 0; q < 4; q++) {
            float zq = __fmul_rn(qv[q], qscale);
            float zn = __fdiv_rn(zv[q], nz);
            float dd = __fsub_rn(zq, zn);
            o[q] = __fadd_rn(zn, dd);
            lsum += dd * dd;
        }
    }
    int obase = bn * EDIM + f * C_ + j;
    if (obase + 3 < out_size) {
        float4 ov; ov.x = o[0]; ov.y = o[1]; ov.z = o[2]; ov.w = o[3];
        *reinterpret_cast<float4*>(out + obase) = ov;
    }

    #pragma unroll
    for (int ofs = 16; ofs > 0; ofs >>= 1) lsum += __shfl_xor_sync(0xFFFFFFFFu, lsum, ofs);
    __shared__ float sw[4];
    int lane = threadIdx.x & 31, wid = threadIdx.x >> 5;
    if (lane == 0) sw[wid] = lsum;
    __syncthreads();
    if (threadIdx.x == 0) {
        g_loss_part[t] = (sw[0] + sw[1]) + (sw[2] + sw[3]);
        int p = ZQ_ELEMS + 1 + ((b * 2 + f) << 8) + n;
        if (p < out_size) out[p] = (float)m;
    }
}

// ---------------------------------------------------------------------------
// 6) final loss: deterministic fixed-order reduction of 8192 partials.
// ---------------------------------------------------------------------------
__global__ void loss_kernel(float* __restrict__ out, int out_size) {
    __shared__ float sh[256];
    float s = 0.f;
    for (int i = threadIdx.x; i < NTOK; i += 256) s += g_loss_part[i];
    sh[threadIdx.x] = s;
    __syncthreads();
    for (int st = 128; st > 0; st >>= 1) {
        if (threadIdx.x < st) sh[threadIdx.x] += sh[threadIdx.x + st];
        __syncthreads();
    }
    if (threadIdx.x == 0 && out_size > ZQ_ELEMS) {
        float mean = sh[0] / (float)ZQ_ELEMS;
        out[ZQ_ELEMS] = __fadd_rn(__fmul_rn(0.25f, mean), mean);
    }
}

// ---------------------------------------------------------------------------
extern "C" void kernel_launch(void* const* d_in, const int* in_sizes, int n_in,
                              void* d_out, int out_size) {
    const float* z   = (const float*)d_in[0];
    const float* emb = (const float*)d_in[1];
    float* out = (float*)d_out;
    (void)in_sizes; (void)n_in;

    norms_kernel<<<(2 * NTOK) / 8, 256>>>(z, emb);                  // 8 warps/block
    convA_kernel<<<(NTOK * C_ / 4 + 255) / 256, 256>>>(z);
    convB_kernel<<<(NTOK * C_ / 4 + 255) / 256, 256>>>(emb);
    wmma_gemm_kernel<<<dim3(NE / 128, BN / 128, F_), 256>>>();
    select_kernel<<<NTOK, 256>>>(z, emb);
    gather_kernel<<<NTOK, 128>>>(z, emb, out, out_size);
    loss_kernel<<<1, 256>>>(out, out_size);
}

// round 10
// speedup vs baseline: 2.8690x; 1.0202x over previous
#include <cuda_runtime.h>
#include <cuda_bf16.h>
#include <mma.h>
#include <cstdint>

using namespace nvcuda;

// Problem constants (fixed shapes from reference)
#define B_    16
#define N_    256
#define EDIM  1024
#define F_    2
#define C_    512          // EDIM / F_
#define NE    4096         // codebook size
#define NTOK  8192         // B_*F_*N_
#define BN    4096         // B_*N_ tokens per codebook
#define ZQ_ELEMS 4194304   // B_*N_*EDIM
#define EPS_  1e-12f
#define MARGIN 0.06f       // > worst-case (bf16 gemm + bf16 storage) error in d-space
#define NTILES 16          // NE / 256 column tiles per codebook

// ---- device scratch (static: no runtime allocations) ----
__device__ float g_invp[NTOK];                 // 1/max(||emb_row||,eps)
__device__ float g_nrmz[NTOK];                 // max(||zf_token||,eps)
__device__ float g_loss_part[NTOK];
__device__ unsigned g_idx[NTOK];               // final selected code per token
__device__ unsigned g_tmin[NTOK * NTILES];     // ord-encoded min d per (token, col-tile)
__device__ __nv_bfloat16 g_zbf[NTOK * C_];     // normalized z in bf16  [f][bn][c]
__device__ __nv_bfloat16 g_pbf[NTOK * C_];     // normalized protos bf16 [f][n][c]
__device__ __nv_bfloat16 g_sbf[(size_t)NTOK * NE];  // approx cos matrix bf16 (64MB)

// float -> order-preserving uint32 (and back)
__device__ __forceinline__ unsigned f2ord(float f) {
    unsigned u = __float_as_uint(f);
    return (u & 0x80000000u) ? ~u : (u | 0x80000000u);
}
__device__ __forceinline__ float ord2f(unsigned o) {
    unsigned u = (o & 0x80000000u) ? (o & 0x7FFFFFFFu) : ~o;
    return __uint_as_float(u);
}
__device__ __forceinline__ uint32_t smem_u32(const void* p) {
    uint32_t a;
    asm("{ .reg .u64 t; cvta.to.shared.u64 t, %1; cvt.u32.u64 %0, t; }" : "=r"(a) : "l"(p));
    return a;
}
#define CP_ASYNC16(smem, gptr) \
    asm volatile("cp.async.cg.shared.global [%0], [%1], 16;" :: "r"(smem), "l"(gptr) : "memory")
#define CP_COMMIT() asm volatile("cp.async.commit_group;" ::: "memory")
#define CP_WAIT(n)  asm volatile("cp.async.wait_group %0;" :: "n"(n) : "memory")

// ---------------------------------------------------------------------------
// 0) init g_tmin
// ---------------------------------------------------------------------------
__global__ void init_kernel() {
    int i = blockIdx.x * blockDim.x + threadIdx.x;
    if (i < NTOK * NTILES) g_tmin[i] = 0xFFFFFFFFu;
}

// ---------------------------------------------------------------------------
// 1) norms: one warp per row. warps [0,8192): prototype rows; [8192,16384): tokens
// ---------------------------------------------------------------------------
__global__ void norms_kernel(const float* __restrict__ z, const float* __restrict__ emb) {
    int gw   = (blockIdx.x * blockDim.x + threadIdx.x) >> 5;
    int lane = threadIdx.x & 31;
    const float* p;
    if (gw < NTOK) {
        p = emb + (size_t)gw * C_;
    } else {
        int t  = gw - NTOK;
        int f  = t >> 12;
        int bn = t & (BN - 1);
        p = z + (size_t)bn * EDIM + f * C_;
    }
    float s = 0.f;
    #pragma unroll
    for (int q = 0; q < 4; q++) {
        float4 v = *reinterpret_cast<const float4*>(p + lane * 4 + q * 128);
        s += v.x * v.x + v.y * v.y + v.z * v.z + v.w * v.w;
    }
    #pragma unroll
    for (int o = 16; o > 0; o >>= 1) s += __shfl_xor_sync(0xFFFFFFFFu, s, o);
    if (lane == 0) {
        float nrm = fmaxf(sqrtf(s), EPS_);
        if (gw < NTOK) g_invp[gw] = 1.0f / nrm;
        else           g_nrmz[gw - NTOK] = nrm;
    }
}

// ---------------------------------------------------------------------------
// 2) convert to bf16 with norms folded in. 4 elems / thread.
// ---------------------------------------------------------------------------
__global__ void convA_kernel(const float* __restrict__ z) {
    int i = blockIdx.x * blockDim.x + threadIdx.x;
    int e = i << 2;
    if (e >= NTOK * C_) return;
    int t  = e >> 9;
    int k  = e & (C_ - 1);
    int f  = t >> 12;
    int bn = t & (BN - 1);
    float inv = 1.0f / g_nrmz[t];
    float4 v = *reinterpret_cast<const float4*>(z + (size_t)bn * EDIM + f * C_ + k);
    __nv_bfloat162 lo = __floats2bfloat162_rn(v.x * inv, v.y * inv);
    __nv_bfloat162 hi = __floats2bfloat162_rn(v.z * inv, v.w * inv);
    *reinterpret_cast<__nv_bfloat162*>(g_zbf + e)     = lo;
    *reinterpret_cast<__nv_bfloat162*>(g_zbf + e + 2) = hi;
}

__global__ void convB_kernel(const float* __restrict__ emb) {
    int i = blockIdx.x * blockDim.x + threadIdx.x;
    int e = i << 2;
    if (e >= NTOK * C_) return;
    int r = e >> 9;
    float sc = g_invp[r];
    float4 v = *reinterpret_cast<const float4*>(emb + e);
    __nv_bfloat162 lo = __floats2bfloat162_rn(v.x * sc, v.y * sc);
    __nv_bfloat162 hi = __floats2bfloat162_rn(v.z * sc, v.w * sc);
    *reinterpret_cast<__nv_bfloat162*>(g_pbf + e)     = lo;
    *reinterpret_cast<__nv_bfloat162*>(g_pbf + e + 2) = hi;
}

// ---------------------------------------------------------------------------
// 3) WMMA GEMM: CTA = 128 tokens x 256 protos, 8 warps each 64x64 (4x4 frags).
//    K=512 in 16 chunks of 32, cp.async double-buffered.
//    Epilogue: s -> bf16 g_sbf, per-(row, col-tile) min d -> g_tmin.
// ---------------------------------------------------------------------------
#define LDPAD 48                         // padded shared row in halves (96 B)
#define A_BYTES (128 * LDPAD * 2)        // 12288
#define B_BYTES (256 * LDPAD * 2)        // 24576
#define BUF_BYTES (A_BYTES + B_BYTES)    // 36864
#define SMEM_DYN (2 * BUF_BYTES)         // 73728

__global__ __launch_bounds__(256)
void wmma_gemm_kernel() {
    extern __shared__ char smem[];
    const uint32_t sb = smem_u32(smem);

    const int tid  = threadIdx.x;
    const int warp = tid >> 5;
    const int lane = tid & 31;
    const int wm = warp >> 2;            // 0..1 : 64-row slab
    const int wn = warp & 3;             // 0..3 : 64-col slab
    const int f  = blockIdx.z;
    const int m0 = blockIdx.y * 128;
    const int n0 = blockIdx.x * 256;

    const __nv_bfloat16* Abase = g_zbf + (size_t)(f * BN + m0) * C_;
    const __nv_bfloat16* Bbase = g_pbf + (size_t)(f * NE + n0) * C_;

    // chunk loader: A 128x32 (512 x 16B), B 256x32 (1024 x 16B)
    auto load_chunk = [&](int c, int buf) {
        uint32_t abuf = sb + buf * BUF_BYTES;
        uint32_t bbuf = abuf + A_BYTES;
        #pragma unroll
        for (int j = 0; j < 2; ++j) {
            int idx = tid + j * 256;               // 0..511
            int row = idx >> 2, seg = idx & 3;
            CP_ASYNC16(abuf + (row * LDPAD + seg * 8) * 2,
                       Abase + (size_t)row * C_ + c * 32 + seg * 8);
        }
        #pragma unroll
        for (int j = 0; j < 4; ++j) {
            int idx = tid + j * 256;               // 0..1023
            int row = idx >> 2, seg = idx & 3;
            CP_ASYNC16(bbuf + (row * LDPAD + seg * 8) * 2,
                       Bbase + (size_t)row * C_ + c * 32 + seg * 8);
        }
    };

    wmma::fragment<wmma::accumulator, 16, 16, 16, float> acc[4][4];
    #pragma unroll
    for (int i = 0; i < 4; i++)
        #pragma unroll
        for (int j = 0; j < 4; j++) wmma::fill_fragment(acc[i][j], 0.0f);

    load_chunk(0, 0);
    CP_COMMIT();

    for (int c = 0; c < 16; ++c) {
        if (c + 1 < 16) { load_chunk(c + 1, (c + 1) & 1); CP_COMMIT(); CP_WAIT(1); }
        else            { CP_WAIT(0); }
        __syncthreads();

        const __nv_bfloat16* As = reinterpret_cast<const __nv_bfloat16*>(smem + (c & 1) * BUF_BYTES);
        const __nv_bfloat16* Bs = reinterpret_cast<const __nv_bfloat16*>(smem + (c & 1) * BUF_BYTES + A_BYTES);
        #pragma unroll
        for (int kk = 0; kk < 32; kk += 16) {
            wmma::fragment<wmma::matrix_a, 16, 16, 16, __nv_bfloat16, wmma::row_major> af[4];
            #pragma unroll
            for (int i = 0; i < 4; i++)
                wmma::load_matrix_sync(af[i], As + (wm * 64 + i * 16) * LDPAD + kk, LDPAD);
            #pragma unroll
            for (int j = 0; j < 4; j++) {
                wmma::fragment<wmma::matrix_b, 16, 16, 16, __nv_bfloat16, wmma::col_major> bf;
                wmma::load_matrix_sync(bf, Bs + (wn * 64 + j * 16) * LDPAD + kk, LDPAD);
                #pragma unroll
                for (int i = 0; i < 4; i++)
                    wmma::mma_sync(acc[i][j], af[i], bf, acc[i][j]);
            }
        }
        __syncthreads();
    }

    // epilogue: stage each 16x16 frag to per-warp smem, write bf16 s + tile row-min
    float* stage = reinterpret_cast<float*>(smem) + warp * 256;
    const int r = lane >> 1, h = lane & 1;      // row 0..15, col half 0..1
    #pragma unroll
    for (int i = 0; i < 4; ++i) {
        const int trow = f * BN + m0 + wm * 64 + i * 16 + r;   // token id
        float smax = -1e30f;
        #pragma unroll
        for (int j = 0; j < 4; ++j) {
            wmma::store_matrix_sync(stage, acc[i][j], 16, wmma::mem_row_major);
            __syncwarp();
            float v[8];
            #pragma unroll
            for (int e = 0; e < 8; ++e) v[e] = stage[r * 16 + h * 8 + e];
            uint32_t* dst = reinterpret_cast<uint32_t*>(
                g_sbf + (size_t)trow * NE + n0 + wn * 64 + j * 16 + h * 8);
            #pragma unroll
            for (int p = 0; p < 4; ++p) {
                __nv_bfloat162 p2 = __floats2bfloat162_rn(v[2 * p], v[2 * p + 1]);
                dst[p] = *reinterpret_cast<uint32_t*>(&p2);
                smax = fmaxf(smax, fmaxf(v[2 * p], v[2 * p + 1]));
            }
            __syncwarp();
        }
        smax = fmaxf(smax, __shfl_xor_sync(0xFFFFFFFFu, smax, 1));
        if (h == 0) {
            float d = __fsub_rn(2.0f, __fmul_rn(2.0f, smax));
            atomicMin(&g_tmin[trow * NTILES + blockIdx.x], f2ord(d));
        }
    }
}

// ---------------------------------------------------------------------------
// 4) select: tile-min pruning + bf16 candidate scan + exact fp32 rescore.
// ---------------------------------------------------------------------------
__global__ __launch_bounds__(256)
void select_kernel(const float* __restrict__ z, const float* __restrict__ emb) {
    const int t  = blockIdx.x;
    const int f  = t >> 12;
    const int bn = t & (BN - 1);

    __shared__ float thr_s;
    __shared__ int cand[512];
    __shared__ int cnt;
    __shared__ unsigned long long bestk;
    __shared__ float ztok[C_];

    // global approx min over the 16 tile mins (warp 0)
    if (threadIdx.x < 32) {
        float v = (threadIdx.x < NTILES) ? ord2f(g_tmin[t * NTILES + threadIdx.x]) : 1e30f;
        #pragma unroll
        for (int o = 16; o > 0; o >>= 1) v = fminf(v, __shfl_xor_sync(0xFFFFFFFFu, v, o));
        if (threadIdx.x == 0) { thr_s = v + MARGIN; cnt = 0; bestk = 0ull; }
    }
    for (int i = threadIdx.x; i < C_; i += 256)
        ztok[i] = z[(size_t)bn * EDIM + f * C_ + i];
    __syncthreads();
    const float thr = thr_s;

    // scan only qualifying tiles (usually 1)
    for (int tile = 0; tile < NTILES; ++tile) {
        if (ord2f(g_tmin[t * NTILES + tile]) > thr) continue;
        float s = __bfloat162float(g_sbf[(size_t)t * NE + tile * 256 + threadIdx.x]);
        float d = __fsub_rn(2.0f, __fmul_rn(2.0f, s));
        if (d <= thr) {
            int p = atomicAdd(&cnt, 1);
            if (p < 512) cand[p] = tile * 256 + threadIdx.x;
        }
    }
    __syncthreads();

    const float invz = 1.0f / g_nrmz[t];
    const int nc = min(cnt, 512);
    const int warp = threadIdx.x >> 5, lane = threadIdx.x & 31;

    for (int c = warp; c < nc; c += 8) {
        int j = cand[c];
        const float* er = emb + (size_t)(f * NE + j) * C_;
        float s = 0.f;
        for (int i = lane; i < C_; i += 32) s += ztok[i] * er[i];
        #pragma unroll
        for (int o = 16; o > 0; o >>= 1) s += __shfl_xor_sync(0xFFFFFFFFu, s, o);
        if (lane == 0) {
            s = s * g_invp[f * NE + j] * invz;
            float d = __fsub_rn(2.0f, __fmul_rn(2.0f, s));
            unsigned long long key =
                ((unsigned long long)(~f2ord(d)) << 32) | (0xFFFFFFFFu - (unsigned)j);
            atomicMax(&bestk, key);
        }
    }
    __syncthreads();
    if (threadIdx.x == 0)
        g_idx[t] = 0xFFFFFFFFu - (unsigned)(bestk & 0xFFFFFFFFull);
}

// ---------------------------------------------------------------------------
// 5) gather + output + per-token loss partial. One block (128 thr) per token.
// ---------------------------------------------------------------------------
__global__ void gather_kernel(const float* __restrict__ z, const float* __restrict__ emb,
                              float* __restrict__ out, int out_size) {
    int t  = blockIdx.x;
    int f  = t >> 12;
    int bn = t & (BN - 1);
    int b  = bn >> 8;
    int n  = bn & 255;

    unsigned m = g_idx[t];
    float qscale = g_invp[m];
    float nz     = g_nrmz[t];

    int j = threadIdx.x * 4;
    float4 vq = *reinterpret_cast<const float4*>(emb + (size_t)m * C_ + j);
    float4 vz = *reinterpret_cast<const float4*>(z + (size_t)bn * EDIM + f * C_ + j);

    float o[4], lsum = 0.f;
    {
        float qv[4] = {vq.x, vq.y, vq.z, vq.w};
        float zv[4] = {vz.x, vz.y, vz.z, vz.w};
        #pragma unroll
        for (int q = 0; q < 4; q++) {
            float zq = __fmul_rn(qv[q], qscale);
            float zn = __fdiv_rn(zv[q], nz);
            float dd = __fsub_rn(zq, zn);
            o[q] = __fadd_rn(zn, dd);
            lsum += dd * dd;
        }
    }
    int obase = bn * EDIM + f * C_ + j;
    if (obase + 3 < out_size) {
        float4 ov; ov.x = o[0]; ov.y = o[1]; ov.z = o[2]; ov.w = o[3];
        *reinterpret_cast<float4*>(out + obase) = ov;
    }

    #pragma unroll
    for (int ofs = 16; ofs > 0; ofs >>= 1) lsum += __shfl_xor_sync(0xFFFFFFFFu, lsum, ofs);
    __shared__ float sw[4];
    int lane = threadIdx.x & 31, wid = threadIdx.x >> 5;
    if (lane == 0) sw[wid] = lsum;
    __syncthreads();
    if (threadIdx.x == 0) {
        g_loss_part[t] = (sw[0] + sw[1]) + (sw[2] + sw[3]);
        int p = ZQ_ELEMS + 1 + ((b * 2 + f) << 8) + n;
        if (p < out_size) out[p] = (float)m;
    }
}

// ---------------------------------------------------------------------------
// 6) final loss: deterministic fixed-order reduction of 8192 partials.
// ---------------------------------------------------------------------------
__global__ void loss_kernel(float* __restrict__ out, int out_size) {
    __shared__ float sh[256];
    float s = 0.f;
    for (int i = threadIdx.x; i < NTOK; i += 256) s += g_loss_part[i];
    sh[threadIdx.x] = s;
    __syncthreads();
    for (int st = 128; st > 0; st >>= 1) {
        if (threadIdx.x < st) sh[threadIdx.x] += sh[threadIdx.x + st];
        __syncthreads();
    }
    if (threadIdx.x == 0 && out_size > ZQ_ELEMS) {
        float mean = sh[0] / (float)ZQ_ELEMS;
        out[ZQ_ELEMS] = __fadd_rn(__fmul_rn(0.25f, mean), mean);
    }
}

// ---------------------------------------------------------------------------
extern "C" void kernel_launch(void* const* d_in, const int* in_sizes, int n_in,
                              void* d_out, int out_size) {
    const float* z   = (const float*)d_in[0];
    const float* emb = (const float*)d_in[1];
    float* out = (float*)d_out;
    (void)in_sizes; (void)n_in;

    cudaFuncSetAttribute(wmma_gemm_kernel, cudaFuncAttributeMaxDynamicSharedMemorySize, SMEM_DYN);

    init_kernel<<<(NTOK * NTILES + 255) / 256, 256>>>();
    norms_kernel<<<(2 * NTOK) / 8, 256>>>(z, emb);
    convA_kernel<<<(NTOK * C_ / 4 + 255) / 256, 256>>>(z);
    convB_kernel<<<(NTOK * C_ / 4 + 255) / 256, 256>>>(emb);
    wmma_gemm_kernel<<<dim3(NE / 256, BN / 128, F_), 256, SMEM_DYN>>>();
    select_kernel<<<NTOK, 256>>>(z, emb);
    gather_kernel<<<NTOK, 128>>>(z, emb, out, out_size);
    loss_kernel<<<1, 256>>>(out, out_size);
}

// round 11
// speedup vs baseline: 2.9088x; 1.0139x over previous
#include <cuda_runtime.h>
#include <cuda_bf16.h>
#include <mma.h>
#include <cstdint>

using namespace nvcuda;

// Problem constants (fixed shapes from reference)
#define B_    16
#define N_    256
#define EDIM  1024
#define F_    2
#define C_    512          // EDIM / F_
#define NE    4096         // codebook size
#define NTOK  8192         // B_*F_*N_
#define BN    4096         // B_*N_ tokens per codebook
#define ZQ_ELEMS 4194304   // B_*N_*EDIM
#define EPS_  1e-12f
#define MARGIN 0.06f       // > worst-case (bf16 gemm + bf16 storage) error in d-space
#define NTILES 16          // NE / 256 column tiles per codebook

// ---- device scratch (static: no runtime allocations) ----
__device__ float g_invp[NTOK];                 // 1/max(||emb_row||,eps)
__device__ float g_nrmz[NTOK];                 // max(||zf_token||,eps)
__device__ float g_loss_part[NTOK];
__device__ unsigned g_tmin[NTOK * NTILES];     // ord-encoded min d per (token, col-tile)
__device__ __nv_bfloat16 g_zbf[NTOK * C_];     // normalized z in bf16  [f][bn][c]
__device__ __nv_bfloat16 g_pbf[NTOK * C_];     // normalized protos bf16 [f][n][c]
__device__ __nv_bfloat16 g_sbf[(size_t)NTOK * NE];  // approx cos matrix bf16 (64MB)

// float -> order-preserving uint32 (and back)
__device__ __forceinline__ unsigned f2ord(float f) {
    unsigned u = __float_as_uint(f);
    return (u & 0x80000000u) ? ~u : (u | 0x80000000u);
}
__device__ __forceinline__ float ord2f(unsigned o) {
    unsigned u = (o & 0x80000000u) ? (o & 0x7FFFFFFFu) : ~o;
    return __uint_as_float(u);
}
__device__ __forceinline__ uint32_t smem_u32(const void* p) {
    uint32_t a;
    asm("{ .reg .u64 t; cvta.to.shared.u64 t, %1; cvt.u32.u64 %0, t; }" : "=r"(a) : "l"(p));
    return a;
}
#define CP_ASYNC16(smem, gptr) \
    asm volatile("cp.async.cg.shared.global [%0], [%1], 16;" :: "r"(smem), "l"(gptr) : "memory")
#define CP_COMMIT() asm volatile("cp.async.commit_group;" ::: "memory")
#define CP_WAIT(n)  asm volatile("cp.async.wait_group %0;" :: "n"(n) : "memory")

// ---------------------------------------------------------------------------
// 1) fused norms + bf16 convert. One 128-thread block per row.
//    rows [0,8192): emb rows -> g_invp, g_pbf ; rows [8192,16384): tokens -> g_nrmz, g_zbf
// ---------------------------------------------------------------------------
__global__ __launch_bounds__(128)
void normconv_kernel(const float* __restrict__ z, const float* __restrict__ emb) {
    const int rid = blockIdx.x;
    const int tid = threadIdx.x;
    const bool is_emb = rid < NTOK;

    const float* src;
    __nv_bfloat16* dst;
    if (is_emb) {
        src = emb + (size_t)rid * C_;
        dst = g_pbf + (size_t)rid * C_;
    } else {
        int t  = rid - NTOK;
        int f  = t >> 12;
        int bn = t & (BN - 1);
        src = z + (size_t)bn * EDIM + f * C_;
        dst = g_zbf + (size_t)t * C_;
    }

    float4 v = *reinterpret_cast<const float4*>(src + tid * 4);
    float s = v.x * v.x + v.y * v.y + v.z * v.z + v.w * v.w;
    #pragma unroll
    for (int o = 16; o > 0; o >>= 1) s += __shfl_xor_sync(0xFFFFFFFFu, s, o);
    __shared__ float sw[4];
    __shared__ float inv_s;
    int lane = tid & 31, wid = tid >> 5;
    if (lane == 0) sw[wid] = s;
    __syncthreads();
    if (tid == 0) {
        float tot = (sw[0] + sw[1]) + (sw[2] + sw[3]);
        float nrm = fmaxf(sqrtf(tot), EPS_);
        float inv = 1.0f / nrm;
        inv_s = inv;
        if (is_emb) g_invp[rid] = inv;
        else        g_nrmz[rid - NTOK] = nrm;
    }
    __syncthreads();
    float inv = inv_s;
    __nv_bfloat162 lo = __floats2bfloat162_rn(v.x * inv, v.y * inv);
    __nv_bfloat162 hi = __floats2bfloat162_rn(v.z * inv, v.w * inv);
    uint2 pk;
    pk.x = *reinterpret_cast<uint32_t*>(&lo);
    pk.y = *reinterpret_cast<uint32_t*>(&hi);
    *reinterpret_cast<uint2*>(dst + tid * 4) = pk;
}

// ---------------------------------------------------------------------------
// 2) WMMA GEMM: CTA = 128 tokens x 256 protos, 8 warps each 64x64 (4x4 frags).
//    K=512 in 16 chunks of 32, cp.async 3-stage pipeline.
//    Epilogue: s -> bf16 g_sbf, per-(row, col-tile) min d -> g_tmin (plain store).
// ---------------------------------------------------------------------------
#define LDPAD 48                         // padded shared row in halves (96 B)
#define A_BYTES (128 * LDPAD * 2)        // 12288
#define B_BYTES (256 * LDPAD * 2)        // 24576
#define BUF_BYTES (A_BYTES + B_BYTES)    // 36864
#define NSTAGE 3
#define SMEM_DYN (NSTAGE * BUF_BYTES)    // 110592

__global__ __launch_bounds__(256)
void wmma_gemm_kernel() {
    extern __shared__ char smem[];
    const uint32_t sb = smem_u32(smem);

    const int tid  = threadIdx.x;
    const int warp = tid >> 5;
    const int lane = tid & 31;
    const int wm = warp >> 2;            // 0..1 : 64-row slab
    const int wn = warp & 3;             // 0..3 : 64-col slab
    const int f  = blockIdx.z;
    const int m0 = blockIdx.y * 128;
    const int n0 = blockIdx.x * 256;

    const __nv_bfloat16* Abase = g_zbf + (size_t)(f * BN + m0) * C_;
    const __nv_bfloat16* Bbase = g_pbf + (size_t)(f * NE + n0) * C_;

    auto load_chunk = [&](int c, int buf) {
        uint32_t abuf = sb + buf * BUF_BYTES;
        uint32_t bbuf = abuf + A_BYTES;
        #pragma unroll
        for (int j = 0; j < 2; ++j) {
            int idx = tid + j * 256;               // 0..511
            int row = idx >> 2, seg = idx & 3;
            CP_ASYNC16(abuf + (row * LDPAD + seg * 8) * 2,
                       Abase + (size_t)row * C_ + c * 32 + seg * 8);
        }
        #pragma unroll
        for (int j = 0; j < 4; ++j) {
            int idx = tid + j * 256;               // 0..1023
            int row = idx >> 2, seg = idx & 3;
            CP_ASYNC16(bbuf + (row * LDPAD + seg * 8) * 2,
                       Bbase + (size_t)row * C_ + c * 32 + seg * 8);
        }
    };

    wmma::fragment<wmma::accumulator, 16, 16, 16, float> acc[4][4];
    #pragma unroll
    for (int i = 0; i < 4; i++)
        #pragma unroll
        for (int j = 0; j < 4; j++) wmma::fill_fragment(acc[i][j], 0.0f);

    load_chunk(0, 0); CP_COMMIT();
    load_chunk(1, 1); CP_COMMIT();

    int buf = 0;
    for (int c = 0; c < 16; ++c) {
        if (c + 2 < 16) {
            load_chunk(c + 2, (c + 2) % NSTAGE);
            CP_COMMIT();
            CP_WAIT(2);
        } else if (c + 1 < 16) {
            CP_WAIT(1);
        } else {
            CP_WAIT(0);
        }
        __syncthreads();

        const __nv_bfloat16* As = reinterpret_cast<const __nv_bfloat16*>(smem + buf * BUF_BYTES);
        const __nv_bfloat16* Bs = reinterpret_cast<const __nv_bfloat16*>(smem + buf * BUF_BYTES + A_BYTES);
        #pragma unroll
        for (int kk = 0; kk < 32; kk += 16) {
            wmma::fragment<wmma::matrix_a, 16, 16, 16, __nv_bfloat16, wmma::row_major> af[4];
            #pragma unroll
            for (int i = 0; i < 4; i++)
                wmma::load_matrix_sync(af[i], As + (wm * 64 + i * 16) * LDPAD + kk, LDPAD);
            #pragma unroll
            for (int j = 0; j < 4; j++) {
                wmma::fragment<wmma::matrix_b, 16, 16, 16, __nv_bfloat16, wmma::col_major> bf;
                wmma::load_matrix_sync(bf, Bs + (wn * 64 + j * 16) * LDPAD + kk, LDPAD);
                #pragma unroll
                for (int i = 0; i < 4; i++)
                    wmma::mma_sync(acc[i][j], af[i], bf, acc[i][j]);
            }
        }
        __syncthreads();
        buf = (buf + 1) % NSTAGE;
    }

    // epilogue: per-warp staging; write bf16 s; 4-warp smem reduce -> g_tmin plain store
    float* stage = reinterpret_cast<float*>(smem) + warp * 256;           // 8KB
    float* rowmax = reinterpret_cast<float*>(smem) + 8 * 256 + 0;         // [128][4]
    const int r = lane >> 1, h = lane & 1;      // row 0..15, col half 0..1
    #pragma unroll
    for (int i = 0; i < 4; ++i) {
        const int lrow = wm * 64 + i * 16 + r;                 // 0..127 within CTA
        const int trow = f * BN + m0 + lrow;                   // token id
        float smax = -1e30f;
        #pragma unroll
        for (int j = 0; j < 4; ++j) {
            wmma::store_matrix_sync(stage, acc[i][j], 16, wmma::mem_row_major);
            __syncwarp();
            float v[8];
            #pragma unroll
            for (int e = 0; e < 8; ++e) v[e] = stage[r * 16 + h * 8 + e];
            uint32_t* dst = reinterpret_cast<uint32_t*>(
                g_sbf + (size_t)trow * NE + n0 + wn * 64 + j * 16 + h * 8);
            #pragma unroll
            for (int p = 0; p < 4; ++p) {
                __nv_bfloat162 p2 = __floats2bfloat162_rn(v[2 * p], v[2 * p + 1]);
                dst[p] = *reinterpret_cast<uint32_t*>(&p2);
                smax = fmaxf(smax, fmaxf(v[2 * p], v[2 * p + 1]));
            }
            __syncwarp();
        }
        smax = fmaxf(smax, __shfl_xor_sync(0xFFFFFFFFu, smax, 1));
        if (h == 0) rowmax[lrow * 4 + wn] = smax;
    }
    __syncthreads();
    if (tid < 128) {
        float s4 = fmaxf(fmaxf(rowmax[tid * 4 + 0], rowmax[tid * 4 + 1]),
                         fmaxf(rowmax[tid * 4 + 2], rowmax[tid * 4 + 3]));
        float d = __fsub_rn(2.0f, __fmul_rn(2.0f, s4));
        g_tmin[(f * BN + m0 + tid) * NTILES + blockIdx.x] = f2ord(d);
    }
}

// ---------------------------------------------------------------------------
// 3) select + gather fused: tile-min pruning, bf16 candidate scan, exact fp32
//    rescore, then straight-through output + loss partial. One block per token.
// ---------------------------------------------------------------------------
__global__ __launch_bounds__(256)
void select_gather_kernel(const float* __restrict__ z, const float* __restrict__ emb,
                          float* __restrict__ out, int out_size) {
    const int t  = blockIdx.x;
    const int f  = t >> 12;
    const int bn = t & (BN - 1);
    const int b  = bn >> 8;
    const int n  = bn & 255;
    const int tid = threadIdx.x;

    __shared__ float thr_s;
    __shared__ int cand[512];
    __shared__ int cnt;
    __shared__ unsigned long long bestk;
    __shared__ float ztok[C_];

    if (tid < 32) {
        float v = (tid < NTILES) ? ord2f(g_tmin[t * NTILES + tid]) : 1e30f;
        #pragma unroll
        for (int o = 16; o > 0; o >>= 1) v = fminf(v, __shfl_xor_sync(0xFFFFFFFFu, v, o));
        if (tid == 0) { thr_s = v + MARGIN; cnt = 0; bestk = 0ull; }
    }
    for (int i = tid; i < C_; i += 256)
        ztok[i] = z[(size_t)bn * EDIM + f * C_ + i];
    __syncthreads();
    const float thr = thr_s;

    for (int tile = 0; tile < NTILES; ++tile) {
        if (ord2f(g_tmin[t * NTILES + tile]) > thr) continue;
        float s = __bfloat162float(g_sbf[(size_t)t * NE + tile * 256 + tid]);
        float d = __fsub_rn(2.0f, __fmul_rn(2.0f, s));
        if (d <= thr) {
            int p = atomicAdd(&cnt, 1);
            if (p < 512) cand[p] = tile * 256 + tid;
        }
    }
    __syncthreads();

    const float nz = g_nrmz[t];
    const float invz = 1.0f / nz;
    const int nc = min(cnt, 512);
    const int warp = tid >> 5, lane = tid & 31;

    for (int c = warp; c < nc; c += 8) {
        int j = cand[c];
        const float* er = emb + (size_t)(f * NE + j) * C_;
        float s = 0.f;
        for (int i = lane; i < C_; i += 32) s += ztok[i] * er[i];
        #pragma unroll
        for (int o = 16; o > 0; o >>= 1) s += __shfl_xor_sync(0xFFFFFFFFu, s, o);
        if (lane == 0) {
            s = s * g_invp[f * NE + j] * invz;
            float d = __fsub_rn(2.0f, __fmul_rn(2.0f, s));
            unsigned long long key =
                ((unsigned long long)(~f2ord(d)) << 32) | (0xFFFFFFFFu - (unsigned)j);
            atomicMax(&bestk, key);
        }
    }
    __syncthreads();

    const unsigned m = 0xFFFFFFFFu - (unsigned)(bestk & 0xFFFFFFFFull);
    const float qscale = g_invp[m];

    // gather: 2 elements per thread, exact reference rounding
    int j = tid * 2;
    float2 vq = *reinterpret_cast<const float2*>(emb + (size_t)m * C_ + j);
    float qv[2] = {vq.x, vq.y};
    float zv[2] = {ztok[j], ztok[j + 1]};
    float o[2], lsum = 0.f;
    #pragma unroll
    for (int q = 0; q < 2; q++) {
        float zq = __fmul_rn(qv[q], qscale);
        float zn = __fdiv_rn(zv[q], nz);
        float dd = __fsub_rn(zq, zn);
        o[q] = __fadd_rn(zn, dd);
        lsum += dd * dd;
    }
    int obase = bn * EDIM + f * C_ + j;
    if (obase + 1 < out_size) {
        float2 ov; ov.x = o[0]; ov.y = o[1];
        *reinterpret_cast<float2*>(out + obase) = ov;
    }

    #pragma unroll
    for (int ofs = 16; ofs > 0; ofs >>= 1) lsum += __shfl_xor_sync(0xFFFFFFFFu, lsum, ofs);
    __shared__ float sw[8];
    if (lane == 0) sw[warp] = lsum;
    __syncthreads();
    if (tid == 0) {
        float tot = ((sw[0] + sw[1]) + (sw[2] + sw[3])) + ((sw[4] + sw[5]) + (sw[6] + sw[7]));
        g_loss_part[t] = tot;
        int p = ZQ_ELEMS + 1 + ((b * 2 + f) << 8) + n;
        if (p < out_size) out[p] = (float)m;
    }
}

// ---------------------------------------------------------------------------
// 4) final loss: deterministic fixed-order reduction of 8192 partials.
// ---------------------------------------------------------------------------
__global__ void loss_kernel(float* __restrict__ out, int out_size) {
    __shared__ float sh[256];
    float s = 0.f;
    for (int i = threadIdx.x; i < NTOK; i += 256) s += g_loss_part[i];
    sh[threadIdx.x] = s;
    __syncthreads();
    for (int st = 128; st > 0; st >>= 1) {
        if (threadIdx.x < st) sh[threadIdx.x] += sh[threadIdx.x + st];
        __syncthreads();
    }
    if (threadIdx.x == 0 && out_size > ZQ_ELEMS) {
        float mean = sh[0] / (float)ZQ_ELEMS;
        out[ZQ_ELEMS] = __fadd_rn(__fmul_rn(0.25f, mean), mean);
    }
}

// ---------------------------------------------------------------------------
extern "C" void kernel_launch(void* const* d_in, const int* in_sizes, int n_in,
                              void* d_out, int out_size) {
    const float* z   = (const float*)d_in[0];
    const float* emb = (const float*)d_in[1];
    float* out = (float*)d_out;
    (void)in_sizes; (void)n_in;

    cudaFuncSetAttribute(wmma_gemm_kernel, cudaFuncAttributeMaxDynamicSharedMemorySize, SMEM_DYN);

    normconv_kernel<<<2 * NTOK, 128>>>(z, emb);
    wmma_gemm_kernel<<<dim3(NE / 256, BN / 128, F_), 256, SMEM_DYN>>>();
    select_gather_kernel<<<NTOK, 256>>>(z, emb, out, out_size);
    loss_kernel<<<1, 256>>>(out, out_size);
}